// round 6
// baseline (speedup 1.0000x reference)
#include <cuda_runtime.h>
#include <cuda_fp16.h>
#include <cstdint>
#include <math.h>

#define THREADS 128
#define NITER   32
#define BM      128
#define SCALEQ  0.3535533905932738f    // 8^-0.5
#define SCALEK  0.5100697280f          // log2(e) * 8^-0.5  (exp -> ex2)
#define ONES    0x3C003C00u            // fp16x2 {1,1}

// smem layout (bytes)
#define SM_Q       0                   // 64 c-rows x 256B (128 t fp16) = 16384
#define SM_BUF     16384               // 2 stages x (K 8192 + V 8192)
#define TILE_K     8192
#define BUF_STRIDE 16384
#define SMEM_BYTES 49152               // also covers epilogue [128][65] f32 (33280)

__device__ __forceinline__ uint32_t smem_u32(const void* p) {
    uint32_t a;
    asm("{ .reg .u64 t; cvta.to.shared.u64 t, %1; cvt.u32.u64 %0, t; }" : "=r"(a) : "l"(p));
    return a;
}
__device__ __forceinline__ uint32_t h2pack(float lo, float hi) {
    uint32_t r;
    asm("cvt.rn.f16x2.f32 %0, %1, %2;" : "=r"(r) : "f"(hi), "f"(lo));
    return r;
}
__device__ __forceinline__ float ex2f(float x) {
    float r;
    asm("ex2.approx.ftz.f32 %0, %1;" : "=f"(r) : "f"(x));
    return r;
}
__device__ __forceinline__ void ldsm4(uint32_t* r, uint32_t a) {
    asm volatile("ldmatrix.sync.aligned.m8n8.x4.shared.b16 {%0,%1,%2,%3}, [%4];"
                 : "=r"(r[0]), "=r"(r[1]), "=r"(r[2]), "=r"(r[3]) : "r"(a));
}
__device__ __forceinline__ void ldsm4t(uint32_t* r, uint32_t a) {
    asm volatile("ldmatrix.sync.aligned.m8n8.x4.trans.shared.b16 {%0,%1,%2,%3}, [%4];"
                 : "=r"(r[0]), "=r"(r[1]), "=r"(r[2]), "=r"(r[3]) : "r"(a));
}
__device__ __forceinline__ void mma16(float* d, const uint32_t* a, uint32_t b0, uint32_t b1) {
    asm volatile("mma.sync.aligned.m16n8k16.row.col.f32.f16.f16.f32 "
                 "{%0,%1,%2,%3}, {%4,%5,%6,%7}, {%8,%9}, {%0,%1,%2,%3};"
                 : "+f"(d[0]), "+f"(d[1]), "+f"(d[2]), "+f"(d[3])
                 : "r"(a[0]), "r"(a[1]), "r"(a[2]), "r"(a[3]), "r"(b0), "r"(b1));
}
__device__ __forceinline__ uint4 pack8(float4 x, float4 y, float s) {
    uint4 u;
    u.x = h2pack(x.x * s, x.y * s);
    u.y = h2pack(x.z * s, x.w * s);
    u.z = h2pack(y.x * s, y.y * s);
    u.w = h2pack(y.z * s, y.w * s);
    return u;
}

__global__ void __launch_bounds__(THREADS, 2)
attn_o2(const float* __restrict__ qkv, float* __restrict__ out) {
    extern __shared__ char smem[];
    const uint32_t S = smem_u32(smem);
    const int tid = threadIdx.x, lane = tid & 31, warp = tid >> 5;
    const int j = lane & 7, grp = lane >> 3, g = lane >> 2, tg = lane & 3;
    const int m0 = warp * 32;
    const int qblk = blockIdx.x, bh = blockIdx.y;
    const int b = bh >> 3, h = bh & 7;
    const float* basep = qkv + ((long)b * 1536 + h * 192) * 2048;
    const float* qp = basep;
    const float* kp = basep + 64L * 2048;
    const float* vp = basep + 128L * 2048;

    // ---- stage Q tile as fp16 [c][t] (256B rows, XOR-swizzled), scaled ----
#pragma unroll
    for (int rep = 0; rep < 4; rep++) {
        int idx = tid + rep * THREADS;
        int c = idx >> 3, t16 = (idx & 7) << 4;
        const float* src = qp + (long)c * 2048 + qblk * BM + t16;
        float4 f0 = *(const float4*)(src);
        float4 f1 = *(const float4*)(src + 4);
        float4 f2 = *(const float4*)(src + 8);
        float4 f3 = *(const float4*)(src + 12);
        uint32_t xr = (uint32_t)(c & 7) << 4;
        *(uint4*)(smem + SM_Q + (c << 8) + (((t16 << 1))      ^ xr)) = pack8(f0, f1, SCALEQ);
        *(uint4*)(smem + SM_Q + (c << 8) + (((t16 << 1) + 16) ^ xr)) = pack8(f2, f3, SCALEQ);
    }

    // ---- stage K/V tile 0 ----
    const int cst = tid >> 1, sst = (tid & 1) << 5;   // c 0..63, s base 0/32
    const uint32_t xrs = (uint32_t)(cst & 7) << 4;
    const uint32_t bcol = (uint32_t)sst << 1;         // byte col base
    {
        const float* ks = kp + (long)cst * 2048 + sst;
        const float* vs = vp + (long)cst * 2048 + sst;
        char* kd = smem + SM_BUF + (cst << 7);
        char* vd = kd + TILE_K;
#pragma unroll
        for (int q = 0; q < 4; q++) {
            float4 a = *(const float4*)(ks + q * 8);
            float4 c2 = *(const float4*)(ks + q * 8 + 4);
            *(uint4*)(kd + ((bcol + q * 16) ^ xrs)) = pack8(a, c2, SCALEK);
            float4 va = *(const float4*)(vs + q * 8);
            float4 vc = *(const float4*)(vs + q * 8 + 4);
            *(uint4*)(vd + ((bcol + q * 16) ^ xrs)) = pack8(va, vc, 1.f);
        }
    }
    __syncthreads();

    // ---- Q fragments -> registers ----
    uint32_t qf[4][8];
    {
        uint32_t rbase = ((uint32_t)(grp >> 1) << 11) + ((uint32_t)j << 8);
        uint32_t c_lo = (((uint32_t)((m0 << 1) + ((grp & 1) << 4))) ^ ((uint32_t)j << 4));
        uint32_t c_hi = (((uint32_t)(((m0 + 16) << 1) + ((grp & 1) << 4))) ^ ((uint32_t)j << 4));
#pragma unroll
        for (int kk = 0; kk < 4; kk++) {
            ldsm4t(&qf[kk][0], S + SM_Q + (kk << 12) + rbase + c_lo);
            ldsm4t(&qf[kk][4], S + SM_Q + (kk << 12) + rbase + c_hi);
        }
    }

    const uint32_t rowk = (uint32_t)(((grp & 1) << 3) + j) << 7;
    const uint32_t rowv = ((uint32_t)(grp >> 1) << 10) + ((uint32_t)j << 7);
    uint32_t sbk[4], sbv[4];
#pragma unroll
    for (int p = 0; p < 4; p++) {
        sbk[p] = (uint32_t)((p << 5) + ((grp >> 1) << 4)) ^ ((uint32_t)j << 4);
        sbv[p] = (uint32_t)((p << 5) + ((grp & 1) << 4)) ^ ((uint32_t)j << 4);
    }

    float oa[16][4];
#pragma unroll
    for (int n = 0; n < 16; n++)
#pragma unroll
        for (int q = 0; q < 4; q++) oa[n][q] = 0.f;
    float rl[4] = {0.f, 0.f, 0.f, 0.f}, rh[4] = {0.f, 0.f, 0.f, 0.f};

    for (int it = 0; it < NITER; ++it) {
        const uint32_t kb = SM_BUF + ((uint32_t)(it & 1) * BUF_STRIDE);
        const uint32_t vb = kb + TILE_K;
        const bool more = (it + 1 < NITER);

        // LDG next K
        float4 nk[8];
        if (more) {
            const float* ks = kp + (it + 1) * 64 + (long)cst * 2048 + sst;
#pragma unroll
            for (int q = 0; q < 8; q++) nk[q] = *(const float4*)(ks + q * 4);
        }

        // ---- S = Q K^T  (M=32 per warp), log2-domain scores ----
        float sa[16][4];
#pragma unroll
        for (int n = 0; n < 16; n++)
#pragma unroll
            for (int q = 0; q < 4; q++) sa[n][q] = 0.f;
#pragma unroll
        for (int kk = 0; kk < 4; kk++) {
            uint32_t basek = S + kb + (kk << 11) + rowk;
#pragma unroll
            for (int np = 0; np < 4; np++) {
                uint32_t r[4];
                ldsm4t(r, basek + sbk[np]);
                mma16(sa[2 * np],         &qf[kk][0], r[0], r[1]);
                mma16(sa[2 * np + 1],     &qf[kk][0], r[2], r[3]);
                mma16(sa[8 + 2 * np],     &qf[kk][4], r[0], r[1]);
                mma16(sa[8 + 2 * np + 1], &qf[kk][4], r[2], r[3]);
            }
        }

        // STS next K; LDG next V
        float4 nv[8];
        if (more) {
            const uint32_t nb = SM_BUF + ((uint32_t)((it + 1) & 1) * BUF_STRIDE);
            char* kd = smem + nb + (cst << 7);
            *(uint4*)(kd + ((bcol)      ^ xrs)) = pack8(nk[0], nk[1], SCALEK);
            *(uint4*)(kd + ((bcol + 16) ^ xrs)) = pack8(nk[2], nk[3], SCALEK);
            *(uint4*)(kd + ((bcol + 32) ^ xrs)) = pack8(nk[4], nk[5], SCALEK);
            *(uint4*)(kd + ((bcol + 48) ^ xrs)) = pack8(nk[6], nk[7], SCALEK);
            const float* vs = vp + (it + 1) * 64 + (long)cst * 2048 + sst;
#pragma unroll
            for (int q = 0; q < 8; q++) nv[q] = *(const float4*)(vs + q * 4);
        }

        // ---- P = 2^S ----
#pragma unroll
        for (int n = 0; n < 16; n++) {
            sa[n][0] = ex2f(sa[n][0]); sa[n][1] = ex2f(sa[n][1]);
            sa[n][2] = ex2f(sa[n][2]); sa[n][3] = ex2f(sa[n][3]);
        }

        // STS next V
        if (more) {
            const uint32_t nb = SM_BUF + ((uint32_t)((it + 1) & 1) * BUF_STRIDE);
            char* vd = smem + nb + TILE_K + (cst << 7);
            *(uint4*)(vd + ((bcol)      ^ xrs)) = pack8(nv[0], nv[1], 1.f);
            *(uint4*)(vd + ((bcol + 16) ^ xrs)) = pack8(nv[2], nv[3], 1.f);
            *(uint4*)(vd + ((bcol + 32) ^ xrs)) = pack8(nv[4], nv[5], 1.f);
            *(uint4*)(vd + ((bcol + 48) ^ xrs)) = pack8(nv[6], nv[7], 1.f);
        }

        // ---- O += P V ; row sums via ones-column MMA ----
#pragma unroll
        for (int kk = 0; kk < 4; kk++) {
            uint32_t al[4], ah[4];
            al[0] = h2pack(sa[2 * kk][0],     sa[2 * kk][1]);
            al[1] = h2pack(sa[2 * kk][2],     sa[2 * kk][3]);
            al[2] = h2pack(sa[2 * kk + 1][0], sa[2 * kk + 1][1]);
            al[3] = h2pack(sa[2 * kk + 1][2], sa[2 * kk + 1][3]);
            ah[0] = h2pack(sa[8 + 2 * kk][0],     sa[8 + 2 * kk][1]);
            ah[1] = h2pack(sa[8 + 2 * kk][2],     sa[8 + 2 * kk][3]);
            ah[2] = h2pack(sa[8 + 2 * kk + 1][0], sa[8 + 2 * kk + 1][1]);
            ah[3] = h2pack(sa[8 + 2 * kk + 1][2], sa[8 + 2 * kk + 1][3]);
            mma16(rl, al, ONES, ONES);
            mma16(rh, ah, ONES, ONES);
            uint32_t basev = S + vb + rowv + sbv[kk];
#pragma unroll
            for (int np = 0; np < 4; np++) {
                uint32_t r[4];
                ldsm4(r, basev + (np << 11));
                mma16(oa[2 * np],         al, r[0], r[1]);
                mma16(oa[2 * np + 1],     al, r[2], r[3]);
                mma16(oa[8 + 2 * np],     ah, r[0], r[1]);
                mma16(oa[8 + 2 * np + 1], ah, r[2], r[3]);
            }
        }
        __syncthreads();
    }

    // ---- epilogue: normalize (row sums already in rl/rh), transpose via smem ----
    const float inv0 = 1.f / rl[0], inv1 = 1.f / rl[2];
    const float inv2 = 1.f / rh[0], inv3 = 1.f / rh[2];

    float* ep = (float*)smem;   // [128][65]
#pragma unroll
    for (int n = 0; n < 8; n++) {
        ep[(m0 + g) * 65      + 8 * n + 2 * tg]     = oa[n][0] * inv0;
        ep[(m0 + g) * 65      + 8 * n + 2 * tg + 1] = oa[n][1] * inv0;
        ep[(m0 + 8 + g) * 65  + 8 * n + 2 * tg]     = oa[n][2] * inv1;
        ep[(m0 + 8 + g) * 65  + 8 * n + 2 * tg + 1] = oa[n][3] * inv1;
        ep[(m0 + 16 + g) * 65 + 8 * n + 2 * tg]     = oa[8 + n][0] * inv2;
        ep[(m0 + 16 + g) * 65 + 8 * n + 2 * tg + 1] = oa[8 + n][1] * inv2;
        ep[(m0 + 24 + g) * 65 + 8 * n + 2 * tg]     = oa[8 + n][2] * inv3;
        ep[(m0 + 24 + g) * 65 + 8 * n + 2 * tg + 1] = oa[8 + n][3] * inv3;
    }
    __syncthreads();

    float* outp = out + ((long)b * 512 + h * 64) * 2048 + qblk * BM;
    for (int i = tid; i < 64 * BM; i += THREADS) {
        int cc = i >> 7, t = i & (BM - 1);
        outp[(long)cc * 2048 + t] = ep[t * 65 + cc];
    }
}

extern "C" void kernel_launch(void* const* d_in, const int* in_sizes, int n_in,
                              void* d_out, int out_size) {
    const float* qkv = (const float*)d_in[0];
    float* out = (float*)d_out;
    cudaFuncSetAttribute(attn_o2, cudaFuncAttributeMaxDynamicSharedMemorySize, SMEM_BYTES);
    dim3 grid(2048 / BM, 32);   // (16, 32) = 512 CTAs, 2 CTAs/SM
    attn_o2<<<grid, THREADS, SMEM_BYTES>>>(qkv, out);
}

// round 7
// speedup vs baseline: 1.6956x; 1.6956x over previous
#include <cuda_runtime.h>
#include <cuda_fp16.h>
#include <cstdint>
#include <math.h>

#define THREADS 256
#define NITER   32
#define BM      256
#define SCALEQ  0.3535533905932738f    // 8^-0.5
#define SCALEK  0.5100697280f          // log2(e) * 8^-0.5  (exp -> ex2)
#define ONES    0x3C003C00u            // fp16x2 {1,1}

// smem layout (bytes)
#define SM_Q       0              // 64 c-rows x 512B (256 t fp16) = 32768
#define SM_BUF     32768          // 2 stages x (K 8192 + V 8192)
#define TILE_K     8192
#define BUF_STRIDE 16384
#define SMEM_BYTES 66560          // epilogue [256][65] f32 needs 66560

__device__ __forceinline__ uint32_t smem_u32(const void* p) {
    uint32_t a;
    asm("{ .reg .u64 t; cvta.to.shared.u64 t, %1; cvt.u32.u64 %0, t; }" : "=r"(a) : "l"(p));
    return a;
}
__device__ __forceinline__ uint32_t h2pack(float lo, float hi) {
    uint32_t r;
    asm("cvt.rn.f16x2.f32 %0, %1, %2;" : "=r"(r) : "f"(hi), "f"(lo));
    return r;
}
__device__ __forceinline__ float ex2f(float x) {
    float r;
    asm("ex2.approx.ftz.f32 %0, %1;" : "=f"(r) : "f"(x));
    return r;
}
__device__ __forceinline__ void ldsm4(uint32_t* r, uint32_t a) {
    asm volatile("ldmatrix.sync.aligned.m8n8.x4.shared.b16 {%0,%1,%2,%3}, [%4];"
                 : "=r"(r[0]), "=r"(r[1]), "=r"(r[2]), "=r"(r[3]) : "r"(a));
}
__device__ __forceinline__ void ldsm4t(uint32_t* r, uint32_t a) {
    asm volatile("ldmatrix.sync.aligned.m8n8.x4.trans.shared.b16 {%0,%1,%2,%3}, [%4];"
                 : "=r"(r[0]), "=r"(r[1]), "=r"(r[2]), "=r"(r[3]) : "r"(a));
}
__device__ __forceinline__ void mma16(float* d, const uint32_t* a, uint32_t b0, uint32_t b1) {
    asm volatile("mma.sync.aligned.m16n8k16.row.col.f32.f16.f16.f32 "
                 "{%0,%1,%2,%3}, {%4,%5,%6,%7}, {%8,%9}, {%0,%1,%2,%3};"
                 : "+f"(d[0]), "+f"(d[1]), "+f"(d[2]), "+f"(d[3])
                 : "r"(a[0]), "r"(a[1]), "r"(a[2]), "r"(a[3]), "r"(b0), "r"(b1));
}
__device__ __forceinline__ uint4 pack8(float4 x, float4 y, float s) {
    uint4 u;
    u.x = h2pack(x.x * s, x.y * s);
    u.y = h2pack(x.z * s, x.w * s);
    u.z = h2pack(y.x * s, y.y * s);
    u.w = h2pack(y.z * s, y.w * s);
    return u;
}

__global__ void __launch_bounds__(THREADS, 1)
attn_r7(const float* __restrict__ qkv, float* __restrict__ out) {
    extern __shared__ char smem[];
    const uint32_t S = smem_u32(smem);
    const int tid = threadIdx.x, lane = tid & 31, warp = tid >> 5;
    const int j = lane & 7, grp = lane >> 3, g = lane >> 2, tg = lane & 3;
    const int m0 = warp * 32;
    const int qblk = blockIdx.x, bh = blockIdx.y;
    const int b = bh >> 3, h = bh & 7;
    const float* basep = qkv + ((long)b * 1536 + h * 192) * 2048;
    const float* qp = basep;
    const float* kp = basep + 64L * 2048;
    const float* vp = basep + 128L * 2048;

    // ---- stage Q tile as fp16 [c][t] (512B rows, XOR-swizzled), scaled ----
#pragma unroll
    for (int rep = 0; rep < 4; rep++) {
        int idx = tid + rep * THREADS;
        int c = idx >> 4, t16 = (idx & 15) << 4;
        const float* src = qp + (long)c * 2048 + qblk * BM + t16;
        float4 f0 = *(const float4*)(src);
        float4 f1 = *(const float4*)(src + 4);
        float4 f2 = *(const float4*)(src + 8);
        float4 f3 = *(const float4*)(src + 12);
        uint32_t xr = (uint32_t)(c & 7) << 4;
        *(uint4*)(smem + SM_Q + (c << 9) + (((t16 << 1))      ^ xr)) = pack8(f0, f1, SCALEQ);
        *(uint4*)(smem + SM_Q + (c << 9) + (((t16 << 1) + 16) ^ xr)) = pack8(f2, f3, SCALEQ);
    }
    __syncthreads();

    // ---- Q fragments -> registers (A-frags via ldmatrix.trans on [c][t]) ----
    uint32_t qf[4][8];
    {
        uint32_t rbase = ((uint32_t)(grp >> 1) << 12) + ((uint32_t)j << 9);
        uint32_t c_lo = (((uint32_t)((m0 << 1) + ((grp & 1) << 4))) ^ ((uint32_t)j << 4));
        uint32_t c_hi = (((uint32_t)(((m0 + 16) << 1) + ((grp & 1) << 4))) ^ ((uint32_t)j << 4));
#pragma unroll
        for (int kk = 0; kk < 4; kk++) {
            ldsm4t(&qf[kk][0], S + SM_Q + (kk << 13) + rbase + c_lo);
            ldsm4t(&qf[kk][4], S + SM_Q + (kk << 13) + rbase + c_hi);
        }
    }

    // per-lane constant ldmatrix offsets for K ([c][s] 128B rows) and V
    const uint32_t rowk = (uint32_t)(((grp & 1) << 3) + j) << 7;
    const uint32_t rowv = ((uint32_t)(grp >> 1) << 10) + ((uint32_t)j << 7);
    uint32_t sbk[4], sbv[4];
#pragma unroll
    for (int p = 0; p < 4; p++) {
        sbk[p] = (uint32_t)((p << 5) + ((grp >> 1) << 4)) ^ ((uint32_t)j << 4);
        sbv[p] = (uint32_t)((p << 5) + ((grp & 1) << 4)) ^ ((uint32_t)j << 4);
    }

    // ---- stage K/V tile 0 ----
    const int cst = tid >> 2, s16 = (tid & 3) << 4;
    const uint32_t xrs = (uint32_t)(cst & 7) << 4;
    const uint32_t bcol = (uint32_t)s16 << 1;
    {
        const float* ks = kp + (long)cst * 2048 + s16;
        const float* vs = vp + (long)cst * 2048 + s16;
        float4 k0 = *(const float4*)(ks),     k1 = *(const float4*)(ks + 4);
        float4 k2 = *(const float4*)(ks + 8), k3 = *(const float4*)(ks + 12);
        float4 v0 = *(const float4*)(vs),     v1 = *(const float4*)(vs + 4);
        float4 v2 = *(const float4*)(vs + 8), v3 = *(const float4*)(vs + 12);
        char* kd = smem + SM_BUF + (cst << 7);
        char* vd = kd + TILE_K;
        *(uint4*)(kd + ((bcol)      ^ xrs)) = pack8(k0, k1, SCALEK);
        *(uint4*)(kd + ((bcol + 16) ^ xrs)) = pack8(k2, k3, SCALEK);
        *(uint4*)(vd + ((bcol)      ^ xrs)) = pack8(v0, v1, 1.f);
        *(uint4*)(vd + ((bcol + 16) ^ xrs)) = pack8(v2, v3, 1.f);
    }
    __syncthreads();

    float oa[16][4];
#pragma unroll
    for (int n = 0; n < 16; n++)
#pragma unroll
        for (int q = 0; q < 4; q++) oa[n][q] = 0.f;
    float rl[4] = {0.f, 0.f, 0.f, 0.f}, rh[4] = {0.f, 0.f, 0.f, 0.f};

    for (int it = 0; it < NITER; ++it) {
        const uint32_t kb = SM_BUF + ((uint32_t)(it & 1) * BUF_STRIDE);
        const uint32_t vb = kb + TILE_K;
        const bool more = (it + 1 < NITER);
        const uint32_t nb = SM_BUF + ((uint32_t)((it + 1) & 1) * BUF_STRIDE);

        // LDG next K (16 regs live through S-mma)
        float4 nk0, nk1, nk2, nk3;
        if (more) {
            const float* ks = kp + (it + 1) * 64 + (long)cst * 2048 + s16;
            nk0 = *(const float4*)(ks);     nk1 = *(const float4*)(ks + 4);
            nk2 = *(const float4*)(ks + 8); nk3 = *(const float4*)(ks + 12);
        }

        // ---- S = Q K^T  (M=32 per warp), log2-domain scores ----
        float sa[16][4];
#pragma unroll
        for (int n = 0; n < 16; n++)
#pragma unroll
            for (int q = 0; q < 4; q++) sa[n][q] = 0.f;
#pragma unroll
        for (int kk = 0; kk < 4; kk++) {
            uint32_t basek = S + kb + (kk << 11) + rowk;
#pragma unroll
            for (int np = 0; np < 4; np++) {
                uint32_t r[4];
                ldsm4t(r, basek + sbk[np]);
                mma16(sa[2 * np],         &qf[kk][0], r[0], r[1]);
                mma16(sa[2 * np + 1],     &qf[kk][0], r[2], r[3]);
                mma16(sa[8 + 2 * np],     &qf[kk][4], r[0], r[1]);
                mma16(sa[8 + 2 * np + 1], &qf[kk][4], r[2], r[3]);
            }
        }

        // STS next K; LDG next V
        float4 nv0, nv1, nv2, nv3;
        if (more) {
            char* kd = smem + nb + (cst << 7);
            *(uint4*)(kd + ((bcol)      ^ xrs)) = pack8(nk0, nk1, SCALEK);
            *(uint4*)(kd + ((bcol + 16) ^ xrs)) = pack8(nk2, nk3, SCALEK);
            const float* vs = vp + (it + 1) * 64 + (long)cst * 2048 + s16;
            nv0 = *(const float4*)(vs);     nv1 = *(const float4*)(vs + 4);
            nv2 = *(const float4*)(vs + 8); nv3 = *(const float4*)(vs + 12);
        }

        // ---- P = 2^S ----
#pragma unroll
        for (int n = 0; n < 16; n++) {
            sa[n][0] = ex2f(sa[n][0]); sa[n][1] = ex2f(sa[n][1]);
            sa[n][2] = ex2f(sa[n][2]); sa[n][3] = ex2f(sa[n][3]);
        }

        // STS next V
        if (more) {
            char* vd = smem + nb + TILE_K + (cst << 7);
            *(uint4*)(vd + ((bcol)      ^ xrs)) = pack8(nv0, nv1, 1.f);
            *(uint4*)(vd + ((bcol + 16) ^ xrs)) = pack8(nv2, nv3, 1.f);
        }

        // ---- O += P V ; row sums via ones-column MMA ----
#pragma unroll
        for (int kk = 0; kk < 4; kk++) {
            uint32_t al[4], ah[4];
            al[0] = h2pack(sa[2 * kk][0],     sa[2 * kk][1]);
            al[1] = h2pack(sa[2 * kk][2],     sa[2 * kk][3]);
            al[2] = h2pack(sa[2 * kk + 1][0], sa[2 * kk + 1][1]);
            al[3] = h2pack(sa[2 * kk + 1][2], sa[2 * kk + 1][3]);
            ah[0] = h2pack(sa[8 + 2 * kk][0],     sa[8 + 2 * kk][1]);
            ah[1] = h2pack(sa[8 + 2 * kk][2],     sa[8 + 2 * kk][3]);
            ah[2] = h2pack(sa[8 + 2 * kk + 1][0], sa[8 + 2 * kk + 1][1]);
            ah[3] = h2pack(sa[8 + 2 * kk + 1][2], sa[8 + 2 * kk + 1][3]);
            mma16(rl, al, ONES, ONES);
            mma16(rh, ah, ONES, ONES);
            uint32_t basev = S + vb + rowv + sbv[kk];
#pragma unroll
            for (int np = 0; np < 4; np++) {
                uint32_t r[4];
                ldsm4(r, basev + (np << 11));
                mma16(oa[2 * np],         al, r[0], r[1]);
                mma16(oa[2 * np + 1],     al, r[2], r[3]);
                mma16(oa[8 + 2 * np],     ah, r[0], r[1]);
                mma16(oa[8 + 2 * np + 1], ah, r[2], r[3]);
            }
        }
        __syncthreads();
    }

    // ---- epilogue: normalize (row sums in rl/rh C-frags), transpose via smem ----
    const float inv0 = 1.f / rl[0], inv1 = 1.f / rl[2];
    const float inv2 = 1.f / rh[0], inv3 = 1.f / rh[2];

    float* ep = (float*)smem;   // [256][65]
#pragma unroll
    for (int n = 0; n < 8; n++) {
        ep[(m0 + g) * 65      + 8 * n + 2 * tg]     = oa[n][0] * inv0;
        ep[(m0 + g) * 65      + 8 * n + 2 * tg + 1] = oa[n][1] * inv0;
        ep[(m0 + 8 + g) * 65  + 8 * n + 2 * tg]     = oa[n][2] * inv1;
        ep[(m0 + 8 + g) * 65  + 8 * n + 2 * tg + 1] = oa[n][3] * inv1;
        ep[(m0 + 16 + g) * 65 + 8 * n + 2 * tg]     = oa[8 + n][0] * inv2;
        ep[(m0 + 16 + g) * 65 + 8 * n + 2 * tg + 1] = oa[8 + n][1] * inv2;
        ep[(m0 + 24 + g) * 65 + 8 * n + 2 * tg]     = oa[8 + n][2] * inv3;
        ep[(m0 + 24 + g) * 65 + 8 * n + 2 * tg + 1] = oa[8 + n][3] * inv3;
    }
    __syncthreads();

    float* outp = out + ((long)b * 512 + h * 64) * 2048 + qblk * BM;
    for (int i = tid; i < 64 * BM; i += THREADS) {
        int cc = i >> 8, t = i & (BM - 1);
        outp[(long)cc * 2048 + t] = ep[t * 65 + cc];
    }
}

extern "C" void kernel_launch(void* const* d_in, const int* in_sizes, int n_in,
                              void* d_out, int out_size) {
    const float* qkv = (const float*)d_in[0];
    float* out = (float*)d_out;
    cudaFuncSetAttribute(attn_r7, cudaFuncAttributeMaxDynamicSharedMemorySize, SMEM_BYTES);
    dim3 grid(2048 / BM, 32);   // (8, 32) = 256 CTAs
    attn_r7<<<grid, THREADS, SMEM_BYTES>>>(qkv, out);
}

// round 8
// speedup vs baseline: 1.9578x; 1.1546x over previous
#include <cuda_runtime.h>
#include <cuda_fp16.h>
#include <cstdint>
#include <math.h>

#define THREADS 256
#define NITER   32
#define BM      256
#define SCALEQ  0.3535533905932738f    // 8^-0.5
#define SCALEK  0.5100697280f          // log2(e) * 8^-0.5  (exp -> bare ex2)

// smem layout (bytes)
#define SM_Q       0              // 64 c-rows x 512B (256 t fp16) = 32768
#define SM_BUF     32768          // 2 stages x (K 8192 + V 8192)
#define TILE_K     8192
#define BUF_STRIDE 16384
#define SMEM_BYTES 66560          // epilogue [256][65] f32 needs 66560

__device__ __forceinline__ uint32_t smem_u32(const void* p) {
    uint32_t a;
    asm("{ .reg .u64 t; cvta.to.shared.u64 t, %1; cvt.u32.u64 %0, t; }" : "=r"(a) : "l"(p));
    return a;
}
__device__ __forceinline__ uint32_t h2pack(float lo, float hi) {
    uint32_t r;
    asm("cvt.rn.f16x2.f32 %0, %1, %2;" : "=r"(r) : "f"(hi), "f"(lo));
    return r;
}
__device__ __forceinline__ float ex2f(float x) {
    float r;
    asm("ex2.approx.ftz.f32 %0, %1;" : "=f"(r) : "f"(x));
    return r;
}
__device__ __forceinline__ void ldsm4(uint32_t* r, uint32_t a) {
    asm volatile("ldmatrix.sync.aligned.m8n8.x4.shared.b16 {%0,%1,%2,%3}, [%4];"
                 : "=r"(r[0]), "=r"(r[1]), "=r"(r[2]), "=r"(r[3]) : "r"(a));
}
__device__ __forceinline__ void ldsm4t(uint32_t* r, uint32_t a) {
    asm volatile("ldmatrix.sync.aligned.m8n8.x4.trans.shared.b16 {%0,%1,%2,%3}, [%4];"
                 : "=r"(r[0]), "=r"(r[1]), "=r"(r[2]), "=r"(r[3]) : "r"(a));
}
__device__ __forceinline__ void mma16(float* d, const uint32_t* a, uint32_t b0, uint32_t b1) {
    asm volatile("mma.sync.aligned.m16n8k16.row.col.f32.f16.f16.f32 "
                 "{%0,%1,%2,%3}, {%4,%5,%6,%7}, {%8,%9}, {%0,%1,%2,%3};"
                 : "+f"(d[0]), "+f"(d[1]), "+f"(d[2]), "+f"(d[3])
                 : "r"(a[0]), "r"(a[1]), "r"(a[2]), "r"(a[3]), "r"(b0), "r"(b1));
}
__device__ __forceinline__ uint4 pack8(float4 x, float4 y, float s) {
    uint4 u;
    u.x = h2pack(x.x * s, x.y * s);
    u.y = h2pack(x.z * s, x.w * s);
    u.z = h2pack(y.x * s, y.y * s);
    u.w = h2pack(y.z * s, y.w * s);
    return u;
}

__global__ void __launch_bounds__(THREADS, 1)
attn_r8(const float* __restrict__ qkv, float* __restrict__ out) {
    extern __shared__ char smem[];
    const uint32_t S = smem_u32(smem);
    const int tid = threadIdx.x, lane = tid & 31, warp = tid >> 5;
    const int j = lane & 7, grp = lane >> 3, g = lane >> 2, tg = lane & 3;
    const int m0 = warp * 32;
    const int qblk = blockIdx.x, bh = blockIdx.y;
    const int b = bh >> 3, h = bh & 7;
    const float* basep = qkv + ((long)b * 1536 + h * 192) * 2048;
    const float* qp = basep;
    const float* kp = basep + 64L * 2048;
    const float* vp = basep + 128L * 2048;

    // ---- stage Q tile as fp16 [c][t] (512B rows, XOR-swizzled), scaled ----
#pragma unroll
    for (int rep = 0; rep < 4; rep++) {
        int idx = tid + rep * THREADS;
        int c = idx >> 4, t16 = (idx & 15) << 4;
        const float* src = qp + (long)c * 2048 + qblk * BM + t16;
        float4 f0 = *(const float4*)(src);
        float4 f1 = *(const float4*)(src + 4);
        float4 f2 = *(const float4*)(src + 8);
        float4 f3 = *(const float4*)(src + 12);
        uint32_t xr = (uint32_t)(c & 7) << 4;
        *(uint4*)(smem + SM_Q + (c << 9) + (((t16 << 1))      ^ xr)) = pack8(f0, f1, SCALEQ);
        *(uint4*)(smem + SM_Q + (c << 9) + (((t16 << 1) + 16) ^ xr)) = pack8(f2, f3, SCALEQ);
    }
    __syncthreads();

    // ---- Q fragments -> registers (A-frags via ldmatrix.trans on [c][t]) ----
    uint32_t qf[4][8];
    {
        uint32_t rbase = ((uint32_t)(grp >> 1) << 12) + ((uint32_t)j << 9);
        uint32_t c_lo = (((uint32_t)((m0 << 1) + ((grp & 1) << 4))) ^ ((uint32_t)j << 4));
        uint32_t c_hi = (((uint32_t)(((m0 + 16) << 1) + ((grp & 1) << 4))) ^ ((uint32_t)j << 4));
#pragma unroll
        for (int kk = 0; kk < 4; kk++) {
            ldsm4t(&qf[kk][0], S + SM_Q + (kk << 13) + rbase + c_lo);
            ldsm4t(&qf[kk][4], S + SM_Q + (kk << 13) + rbase + c_hi);
        }
    }

    // per-lane constant ldmatrix offsets for K ([c][s] 128B rows) and V
    const uint32_t rowk = (uint32_t)(((grp & 1) << 3) + j) << 7;
    const uint32_t rowv = ((uint32_t)(grp >> 1) << 10) + ((uint32_t)j << 7);
    uint32_t sbk[4], sbv[4];
#pragma unroll
    for (int p = 0; p < 4; p++) {
        sbk[p] = (uint32_t)((p << 5) + ((grp >> 1) << 4)) ^ ((uint32_t)j << 4);
        sbv[p] = (uint32_t)((p << 5) + ((grp & 1) << 4)) ^ ((uint32_t)j << 4);
    }

    // ---- stage K/V tile 0 ----
    const int cst = tid >> 2, s16 = (tid & 3) << 4;
    {
        const float* ks = kp + (long)cst * 2048 + s16;
        const float* vs = vp + (long)cst * 2048 + s16;
        float4 k0 = *(const float4*)(ks),     k1 = *(const float4*)(ks + 4);
        float4 k2 = *(const float4*)(ks + 8), k3 = *(const float4*)(ks + 12);
        float4 v0 = *(const float4*)(vs),     v1 = *(const float4*)(vs + 4);
        float4 v2 = *(const float4*)(vs + 8), v3 = *(const float4*)(vs + 12);
        uint32_t xr = (uint32_t)(cst & 7) << 4;
        char* kd = smem + SM_BUF + (cst << 7);
        char* vd = kd + TILE_K;
        *(uint4*)(kd + (((s16 << 1))      ^ xr)) = pack8(k0, k1, SCALEK);
        *(uint4*)(kd + (((s16 << 1) + 16) ^ xr)) = pack8(k2, k3, SCALEK);
        *(uint4*)(vd + (((s16 << 1))      ^ xr)) = pack8(v0, v1, 1.f);
        *(uint4*)(vd + (((s16 << 1) + 16) ^ xr)) = pack8(v2, v3, 1.f);
    }
    __syncthreads();

    float oa[16][4];
#pragma unroll
    for (int n = 0; n < 16; n++)
#pragma unroll
        for (int q = 0; q < 4; q++) oa[n][q] = 0.f;
    float ls0 = 0.f, ls1 = 0.f, ls2 = 0.f, ls3 = 0.f;

    for (int it = 0; it < NITER; ++it) {
        const uint32_t kb = SM_BUF + ((uint32_t)(it & 1) * BUF_STRIDE);
        const uint32_t vb = kb + TILE_K;

        // batched prefetch of next tile (32 regs, max MLP)
        float4 pk0, pk1, pk2, pk3, pv0, pv1, pv2, pv3;
        if (it + 1 < NITER) {
            const float* ks = kp + (it + 1) * 64 + (long)cst * 2048 + s16;
            const float* vs = vp + (it + 1) * 64 + (long)cst * 2048 + s16;
            pk0 = *(const float4*)(ks);     pk1 = *(const float4*)(ks + 4);
            pk2 = *(const float4*)(ks + 8); pk3 = *(const float4*)(ks + 12);
            pv0 = *(const float4*)(vs);     pv1 = *(const float4*)(vs + 4);
            pv2 = *(const float4*)(vs + 8); pv3 = *(const float4*)(vs + 12);
        }

        // ---- S = Q K^T  (M=32 per warp), log2-domain scores ----
        float sa[16][4];
#pragma unroll
        for (int n = 0; n < 16; n++)
#pragma unroll
            for (int q = 0; q < 4; q++) sa[n][q] = 0.f;
#pragma unroll
        for (int kk = 0; kk < 4; kk++) {
            uint32_t basek = S + kb + (kk << 11) + rowk;
#pragma unroll
            for (int np = 0; np < 4; np++) {
                uint32_t r[4];
                ldsm4t(r, basek + sbk[np]);
                mma16(sa[2 * np],         &qf[kk][0], r[0], r[1]);
                mma16(sa[2 * np + 1],     &qf[kk][0], r[2], r[3]);
                mma16(sa[8 + 2 * np],     &qf[kk][4], r[0], r[1]);
                mma16(sa[8 + 2 * np + 1], &qf[kk][4], r[2], r[3]);
            }
        }

        // ---- P = 2^S (bare ex2), row sums via FADD ----
#pragma unroll
        for (int n = 0; n < 8; n++) {
            sa[n][0] = ex2f(sa[n][0]); sa[n][1] = ex2f(sa[n][1]);
            sa[n][2] = ex2f(sa[n][2]); sa[n][3] = ex2f(sa[n][3]);
            ls0 += sa[n][0] + sa[n][1];
            ls1 += sa[n][2] + sa[n][3];
        }
#pragma unroll
        for (int n = 8; n < 16; n++) {
            sa[n][0] = ex2f(sa[n][0]); sa[n][1] = ex2f(sa[n][1]);
            sa[n][2] = ex2f(sa[n][2]); sa[n][3] = ex2f(sa[n][3]);
            ls2 += sa[n][0] + sa[n][1];
            ls3 += sa[n][2] + sa[n][3];
        }

        // store staged next tile (other buffer)
        if (it + 1 < NITER) {
            uint32_t nb = SM_BUF + ((uint32_t)((it + 1) & 1) * BUF_STRIDE);
            uint32_t xr = (uint32_t)(cst & 7) << 4;
            char* kd = smem + nb + (cst << 7);
            char* vd = kd + TILE_K;
            *(uint4*)(kd + (((s16 << 1))      ^ xr)) = pack8(pk0, pk1, SCALEK);
            *(uint4*)(kd + (((s16 << 1) + 16) ^ xr)) = pack8(pk2, pk3, SCALEK);
            *(uint4*)(vd + (((s16 << 1))      ^ xr)) = pack8(pv0, pv1, 1.f);
            *(uint4*)(vd + (((s16 << 1) + 16) ^ xr)) = pack8(pv2, pv3, 1.f);
        }

        // ---- O += P V ----
#pragma unroll
        for (int kk = 0; kk < 4; kk++) {
            uint32_t al[4], ah[4];
            al[0] = h2pack(sa[2 * kk][0],     sa[2 * kk][1]);
            al[1] = h2pack(sa[2 * kk][2],     sa[2 * kk][3]);
            al[2] = h2pack(sa[2 * kk + 1][0], sa[2 * kk + 1][1]);
            al[3] = h2pack(sa[2 * kk + 1][2], sa[2 * kk + 1][3]);
            ah[0] = h2pack(sa[8 + 2 * kk][0],     sa[8 + 2 * kk][1]);
            ah[1] = h2pack(sa[8 + 2 * kk][2],     sa[8 + 2 * kk][3]);
            ah[2] = h2pack(sa[8 + 2 * kk + 1][0], sa[8 + 2 * kk + 1][1]);
            ah[3] = h2pack(sa[8 + 2 * kk + 1][2], sa[8 + 2 * kk + 1][3]);
            uint32_t basev = S + vb + rowv + sbv[kk];
#pragma unroll
            for (int np = 0; np < 4; np++) {
                uint32_t r[4];
                ldsm4(r, basev + (np << 11));
                mma16(oa[2 * np],         al, r[0], r[1]);
                mma16(oa[2 * np + 1],     al, r[2], r[3]);
                mma16(oa[8 + 2 * np],     ah, r[0], r[1]);
                mma16(oa[8 + 2 * np + 1], ah, r[2], r[3]);
            }
        }
        __syncthreads();
    }

    // ---- epilogue: row-sum reduce, normalize, transpose via smem ----
    ls0 += __shfl_xor_sync(0xffffffffu, ls0, 1);
    ls0 += __shfl_xor_sync(0xffffffffu, ls0, 2);
    ls1 += __shfl_xor_sync(0xffffffffu, ls1, 1);
    ls1 += __shfl_xor_sync(0xffffffffu, ls1, 2);
    ls2 += __shfl_xor_sync(0xffffffffu, ls2, 1);
    ls2 += __shfl_xor_sync(0xffffffffu, ls2, 2);
    ls3 += __shfl_xor_sync(0xffffffffu, ls3, 1);
    ls3 += __shfl_xor_sync(0xffffffffu, ls3, 2);
    const float inv0 = 1.f / ls0, inv1 = 1.f / ls1;
    const float inv2 = 1.f / ls2, inv3 = 1.f / ls3;

    float* ep = (float*)smem;   // [256][65]
#pragma unroll
    for (int n = 0; n < 8; n++) {
        ep[(m0 + g) * 65      + 8 * n + 2 * tg]     = oa[n][0] * inv0;
        ep[(m0 + g) * 65      + 8 * n + 2 * tg + 1] = oa[n][1] * inv0;
        ep[(m0 + 8 + g) * 65  + 8 * n + 2 * tg]     = oa[n][2] * inv1;
        ep[(m0 + 8 + g) * 65  + 8 * n + 2 * tg + 1] = oa[n][3] * inv1;
        ep[(m0 + 16 + g) * 65 + 8 * n + 2 * tg]     = oa[8 + n][0] * inv2;
        ep[(m0 + 16 + g) * 65 + 8 * n + 2 * tg + 1] = oa[8 + n][1] * inv2;
        ep[(m0 + 24 + g) * 65 + 8 * n + 2 * tg]     = oa[8 + n][2] * inv3;
        ep[(m0 + 24 + g) * 65 + 8 * n + 2 * tg + 1] = oa[8 + n][3] * inv3;
    }
    __syncthreads();

    float* outp = out + ((long)b * 512 + h * 64) * 2048 + qblk * BM;
    for (int i = tid; i < 64 * BM; i += THREADS) {
        int cc = i >> 8, t = i & (BM - 1);
        outp[(long)cc * 2048 + t] = ep[t * 65 + cc];
    }
}

extern "C" void kernel_launch(void* const* d_in, const int* in_sizes, int n_in,
                              void* d_out, int out_size) {
    const float* qkv = (const float*)d_in[0];
    float* out = (float*)d_out;
    cudaFuncSetAttribute(attn_r8, cudaFuncAttributeMaxDynamicSharedMemorySize, SMEM_BYTES);
    dim3 grid(2048 / BM, 32);   // (8, 32) = 256 CTAs
    attn_r8<<<grid, THREADS, SMEM_BYTES>>>(qkv, out);
}

// round 9
// speedup vs baseline: 2.0617x; 1.0531x over previous
#include <cuda_runtime.h>
#include <cuda_fp16.h>
#include <cstdint>
#include <math.h>

#define THREADS 256
#define NITER   32
#define BM      256
#define SCALEQ  0.3535533905932738f    // 8^-0.5
#define SCALEK  0.5100697280f          // log2(e) * 8^-0.5  (exp -> bare ex2)

// smem layout (bytes)
#define SM_Q       0              // 64 c-rows x 512B (256 t fp16) = 32768
#define SM_BUF     32768          // 4 stages x (K 8192 + V 8192)
#define TILE_K     8192
#define BUF_STRIDE 16384
#define SMEM_BYTES 98304          // 32768 + 4*16384; epilogue (66560) fits

__device__ __forceinline__ uint32_t smem_u32(const void* p) {
    uint32_t a;
    asm("{ .reg .u64 t; cvta.to.shared.u64 t, %1; cvt.u32.u64 %0, t; }" : "=r"(a) : "l"(p));
    return a;
}
__device__ __forceinline__ uint32_t h2pack(float lo, float hi) {
    uint32_t r;
    asm("cvt.rn.f16x2.f32 %0, %1, %2;" : "=r"(r) : "f"(hi), "f"(lo));
    return r;
}
__device__ __forceinline__ float ex2f(float x) {
    float r;
    asm("ex2.approx.ftz.f32 %0, %1;" : "=f"(r) : "f"(x));
    return r;
}
__device__ __forceinline__ void ldsm4(uint32_t* r, uint32_t a) {
    asm volatile("ldmatrix.sync.aligned.m8n8.x4.shared.b16 {%0,%1,%2,%3}, [%4];"
                 : "=r"(r[0]), "=r"(r[1]), "=r"(r[2]), "=r"(r[3]) : "r"(a));
}
__device__ __forceinline__ void ldsm4t(uint32_t* r, uint32_t a) {
    asm volatile("ldmatrix.sync.aligned.m8n8.x4.trans.shared.b16 {%0,%1,%2,%3}, [%4];"
                 : "=r"(r[0]), "=r"(r[1]), "=r"(r[2]), "=r"(r[3]) : "r"(a));
}
__device__ __forceinline__ void mma16(float* d, const uint32_t* a, uint32_t b0, uint32_t b1) {
    asm volatile("mma.sync.aligned.m16n8k16.row.col.f32.f16.f16.f32 "
                 "{%0,%1,%2,%3}, {%4,%5,%6,%7}, {%8,%9}, {%0,%1,%2,%3};"
                 : "+f"(d[0]), "+f"(d[1]), "+f"(d[2]), "+f"(d[3])
                 : "r"(a[0]), "r"(a[1]), "r"(a[2]), "r"(a[3]), "r"(b0), "r"(b1));
}
__device__ __forceinline__ uint4 pack8(float4 x, float4 y, float s) {
    uint4 u;
    u.x = h2pack(x.x * s, x.y * s);
    u.y = h2pack(x.z * s, x.w * s);
    u.z = h2pack(y.x * s, y.y * s);
    u.w = h2pack(y.z * s, y.w * s);
    return u;
}

__global__ void __launch_bounds__(THREADS, 1)
attn_r9(const float* __restrict__ qkv, float* __restrict__ out) {
    extern __shared__ char smem[];
    const uint32_t S = smem_u32(smem);
    const int tid = threadIdx.x, lane = tid & 31, warp = tid >> 5;
    const int j = lane & 7, grp = lane >> 3, g = lane >> 2, tg = lane & 3;
    const int m0 = warp * 32;
    const int qblk = blockIdx.x, bh = blockIdx.y;
    const int b = bh >> 3, h = bh & 7;
    const float* basep = qkv + ((long)b * 1536 + h * 192) * 2048;
    const float* qp = basep;
    const float* kp = basep + 64L * 2048;
    const float* vp = basep + 128L * 2048;

    // ---- stage Q tile as fp16 [c][t] (512B rows, XOR-swizzled), scaled ----
#pragma unroll
    for (int rep = 0; rep < 4; rep++) {
        int idx = tid + rep * THREADS;
        int c = idx >> 4, t16 = (idx & 15) << 4;
        const float* src = qp + (long)c * 2048 + qblk * BM + t16;
        float4 f0 = *(const float4*)(src);
        float4 f1 = *(const float4*)(src + 4);
        float4 f2 = *(const float4*)(src + 8);
        float4 f3 = *(const float4*)(src + 12);
        uint32_t xr = (uint32_t)(c & 7) << 4;
        *(uint4*)(smem + SM_Q + (c << 9) + (((t16 << 1))      ^ xr)) = pack8(f0, f1, SCALEQ);
        *(uint4*)(smem + SM_Q + (c << 9) + (((t16 << 1) + 16) ^ xr)) = pack8(f2, f3, SCALEQ);
    }

    // ---- stage K/V tiles 0 and 1 into ring stages 0,1 ----
    const int cst = tid >> 2, s16 = (tid & 3) << 4;
    const uint32_t xrs = (uint32_t)(cst & 7) << 4;
    const uint32_t bcol = (uint32_t)s16 << 1;
#pragma unroll
    for (int t0 = 0; t0 < 2; t0++) {
        const float* ks = kp + t0 * 64 + (long)cst * 2048 + s16;
        const float* vs = vp + t0 * 64 + (long)cst * 2048 + s16;
        float4 k0 = *(const float4*)(ks),     k1 = *(const float4*)(ks + 4);
        float4 k2 = *(const float4*)(ks + 8), k3 = *(const float4*)(ks + 12);
        float4 v0 = *(const float4*)(vs),     v1 = *(const float4*)(vs + 4);
        float4 v2 = *(const float4*)(vs + 8), v3 = *(const float4*)(vs + 12);
        char* kd = smem + SM_BUF + t0 * BUF_STRIDE + (cst << 7);
        char* vd = kd + TILE_K;
        *(uint4*)(kd + ((bcol)      ^ xrs)) = pack8(k0, k1, SCALEK);
        *(uint4*)(kd + ((bcol + 16) ^ xrs)) = pack8(k2, k3, SCALEK);
        *(uint4*)(vd + ((bcol)      ^ xrs)) = pack8(v0, v1, 1.f);
        *(uint4*)(vd + ((bcol + 16) ^ xrs)) = pack8(v2, v3, 1.f);
    }
    __syncthreads();

    // ---- Q fragments -> registers (A-frags via ldmatrix.trans on [c][t]) ----
    uint32_t qf[4][8];
    {
        uint32_t rbase = ((uint32_t)(grp >> 1) << 12) + ((uint32_t)j << 9);
        uint32_t c_lo = (((uint32_t)((m0 << 1) + ((grp & 1) << 4))) ^ ((uint32_t)j << 4));
        uint32_t c_hi = (((uint32_t)(((m0 + 16) << 1) + ((grp & 1) << 4))) ^ ((uint32_t)j << 4));
#pragma unroll
        for (int kk = 0; kk < 4; kk++) {
            ldsm4t(&qf[kk][0], S + SM_Q + (kk << 13) + rbase + c_lo);
            ldsm4t(&qf[kk][4], S + SM_Q + (kk << 13) + rbase + c_hi);
        }
    }

    // per-lane constant ldmatrix offsets for K ([c][s] 128B rows) and V
    const uint32_t rowk = (uint32_t)(((grp & 1) << 3) + j) << 7;
    const uint32_t rowv = ((uint32_t)(grp >> 1) << 10) + ((uint32_t)j << 7);
    uint32_t sbk[4], sbv[4];
#pragma unroll
    for (int p = 0; p < 4; p++) {
        sbk[p] = (uint32_t)((p << 5) + ((grp >> 1) << 4)) ^ ((uint32_t)j << 4);
        sbv[p] = (uint32_t)((p << 5) + ((grp & 1) << 4)) ^ ((uint32_t)j << 4);
    }

    float oa[16][4];
#pragma unroll
    for (int n = 0; n < 16; n++)
#pragma unroll
        for (int q = 0; q < 4; q++) oa[n][q] = 0.f;
    float ls0 = 0.f, ls1 = 0.f, ls2 = 0.f, ls3 = 0.f;

#pragma unroll 2
    for (int it = 0; it < NITER; ++it) {
        const uint32_t kb = SM_BUF + ((uint32_t)(it & 3) * BUF_STRIDE);
        const uint32_t vb = kb + TILE_K;
        const bool more = (it + 2 < NITER);

        // batched LDG of tile it+2 (distance-2 prefetch, max MLP)
        float4 pk0, pk1, pk2, pk3, pv0, pv1, pv2, pv3;
        if (more) {
            const float* ks = kp + (it + 2) * 64 + (long)cst * 2048 + s16;
            const float* vs = vp + (it + 2) * 64 + (long)cst * 2048 + s16;
            pk0 = *(const float4*)(ks);     pk1 = *(const float4*)(ks + 4);
            pk2 = *(const float4*)(ks + 8); pk3 = *(const float4*)(ks + 12);
            pv0 = *(const float4*)(vs);     pv1 = *(const float4*)(vs + 4);
            pv2 = *(const float4*)(vs + 8); pv3 = *(const float4*)(vs + 12);
        }

        // ---- S = Q K^T  (M=32 per warp), log2-domain scores ----
        float sa[16][4];
#pragma unroll
        for (int n = 0; n < 16; n++)
#pragma unroll
            for (int q = 0; q < 4; q++) sa[n][q] = 0.f;
#pragma unroll
        for (int kk = 0; kk < 4; kk++) {
            uint32_t basek = S + kb + (kk << 11) + rowk;
#pragma unroll
            for (int np = 0; np < 4; np++) {
                uint32_t r[4];
                ldsm4t(r, basek + sbk[np]);
                mma16(sa[2 * np],         &qf[kk][0], r[0], r[1]);
                mma16(sa[2 * np + 1],     &qf[kk][0], r[2], r[3]);
                mma16(sa[8 + 2 * np],     &qf[kk][4], r[0], r[1]);
                mma16(sa[8 + 2 * np + 1], &qf[kk][4], r[2], r[3]);
            }
        }

        // STS tile it+2 into ring stage (it+2)&3 (2-iteration slack)
        if (more) {
            uint32_t nb = SM_BUF + ((uint32_t)((it + 2) & 3) * BUF_STRIDE);
            char* kd = smem + nb + (cst << 7);
            char* vd = kd + TILE_K;
            *(uint4*)(kd + ((bcol)      ^ xrs)) = pack8(pk0, pk1, SCALEK);
            *(uint4*)(kd + ((bcol + 16) ^ xrs)) = pack8(pk2, pk3, SCALEK);
            *(uint4*)(vd + ((bcol)      ^ xrs)) = pack8(pv0, pv1, 1.f);
            *(uint4*)(vd + ((bcol + 16) ^ xrs)) = pack8(pv2, pv3, 1.f);
        }

        // ---- P = 2^S (bare ex2), row sums via FADD ----
#pragma unroll
        for (int n = 0; n < 8; n++) {
            sa[n][0] = ex2f(sa[n][0]); sa[n][1] = ex2f(sa[n][1]);
            sa[n][2] = ex2f(sa[n][2]); sa[n][3] = ex2f(sa[n][3]);
            ls0 += sa[n][0] + sa[n][1];
            ls1 += sa[n][2] + sa[n][3];
        }
#pragma unroll
        for (int n = 8; n < 16; n++) {
            sa[n][0] = ex2f(sa[n][0]); sa[n][1] = ex2f(sa[n][1]);
            sa[n][2] = ex2f(sa[n][2]); sa[n][3] = ex2f(sa[n][3]);
            ls2 += sa[n][0] + sa[n][1];
            ls3 += sa[n][2] + sa[n][3];
        }

        // ---- O += P V ----
#pragma unroll
        for (int kk = 0; kk < 4; kk++) {
            uint32_t al[4], ah[4];
            al[0] = h2pack(sa[2 * kk][0],     sa[2 * kk][1]);
            al[1] = h2pack(sa[2 * kk][2],     sa[2 * kk][3]);
            al[2] = h2pack(sa[2 * kk + 1][0], sa[2 * kk + 1][1]);
            al[3] = h2pack(sa[2 * kk + 1][2], sa[2 * kk + 1][3]);
            ah[0] = h2pack(sa[8 + 2 * kk][0],     sa[8 + 2 * kk][1]);
            ah[1] = h2pack(sa[8 + 2 * kk][2],     sa[8 + 2 * kk][3]);
            ah[2] = h2pack(sa[8 + 2 * kk + 1][0], sa[8 + 2 * kk + 1][1]);
            ah[3] = h2pack(sa[8 + 2 * kk + 1][2], sa[8 + 2 * kk + 1][3]);
            uint32_t basev = S + vb + rowv + sbv[kk];
#pragma unroll
            for (int np = 0; np < 4; np++) {
                uint32_t r[4];
                ldsm4(r, basev + (np << 11));
                mma16(oa[2 * np],         al, r[0], r[1]);
                mma16(oa[2 * np + 1],     al, r[2], r[3]);
                mma16(oa[8 + 2 * np],     ah, r[0], r[1]);
                mma16(oa[8 + 2 * np + 1], ah, r[2], r[3]);
            }
        }
        if (it & 1) __syncthreads();   // one barrier per 2 tiles (4-stage ring)
    }

    // ---- epilogue: row-sum reduce, normalize, transpose via smem ----
    ls0 += __shfl_xor_sync(0xffffffffu, ls0, 1);
    ls0 += __shfl_xor_sync(0xffffffffu, ls0, 2);
    ls1 += __shfl_xor_sync(0xffffffffu, ls1, 1);
    ls1 += __shfl_xor_sync(0xffffffffu, ls1, 2);
    ls2 += __shfl_xor_sync(0xffffffffu, ls2, 1);
    ls2 += __shfl_xor_sync(0xffffffffu, ls2, 2);
    ls3 += __shfl_xor_sync(0xffffffffu, ls3, 1);
    ls3 += __shfl_xor_sync(0xffffffffu, ls3, 2);
    const float inv0 = 1.f / ls0, inv1 = 1.f / ls1;
    const float inv2 = 1.f / ls2, inv3 = 1.f / ls3;

    __syncthreads();   // loop's last iter (odd) synced, but be explicit before reuse
    float* ep = (float*)smem;   // [256][65]
#pragma unroll
    for (int n = 0; n < 8; n++) {
        ep[(m0 + g) * 65      + 8 * n + 2 * tg]     = oa[n][0] * inv0;
        ep[(m0 + g) * 65      + 8 * n + 2 * tg + 1] = oa[n][1] * inv0;
        ep[(m0 + 8 + g) * 65  + 8 * n + 2 * tg]     = oa[n][2] * inv1;
        ep[(m0 + 8 + g) * 65  + 8 * n + 2 * tg + 1] = oa[n][3] * inv1;
        ep[(m0 + 16 + g) * 65 + 8 * n + 2 * tg]     = oa[8 + n][0] * inv2;
        ep[(m0 + 16 + g) * 65 + 8 * n + 2 * tg + 1] = oa[8 + n][1] * inv2;
        ep[(m0 + 24 + g) * 65 + 8 * n + 2 * tg]     = oa[8 + n][2] * inv3;
        ep[(m0 + 24 + g) * 65 + 8 * n + 2 * tg + 1] = oa[8 + n][3] * inv3;
    }
    __syncthreads();

    float* outp = out + ((long)b * 512 + h * 64) * 2048 + qblk * BM;
    for (int i = tid; i < 64 * BM; i += THREADS) {
        int cc = i >> 8, t = i & (BM - 1);
        outp[(long)cc * 2048 + t] = ep[t * 65 + cc];
    }
}

extern "C" void kernel_launch(void* const* d_in, const int* in_sizes, int n_in,
                              void* d_out, int out_size) {
    const float* qkv = (const float*)d_in[0];
    float* out = (float*)d_out;
    cudaFuncSetAttribute(attn_r9, cudaFuncAttributeMaxDynamicSharedMemorySize, SMEM_BYTES);
    dim3 grid(2048 / BM, 32);   // (8, 32) = 256 CTAs
    attn_r9<<<grid, THREADS, SMEM_BYTES>>>(qkv, out);
}